// round 16
// baseline (speedup 1.0000x reference)
#include <cuda_runtime.h>
#include <cuda_bf16.h>
#include <math.h>

// ---------------- problem constants ----------------
#define BB      2
#define CC0     48          // dim
#define NHEADS  2
#define CHD     24          // channels per head
#define DP      32          // padded head dim (bf16 tensors)
#define NTOK    4096        // 64*64
#define NPIX    (BB*NTOK)   // 8192
#define C3      144         // dim*3
#define HID     96
#define HID2    192
#define NSPL    8           // attention KV splits
#define ASTR    28          // accumulator record (floats, 16B aligned): 24 O + l

// ---------------- scratch (device globals; no allocation allowed) ----------
__device__ float g_qkv1[BB*C3*NTOK];
__device__ __nv_bfloat16 g_qb[BB*NHEADS*NTOK*DP];
__device__ __nv_bfloat16 g_kb[BB*NHEADS*NTOK*DP];
__device__ __nv_bfloat16 g_vb[BB*NHEADS*NTOK*DP];
__device__ float g_acc[BB*NHEADS*NTOK*ASTR];       // atomic O/l accumulator
__device__ float g_x1[BB*CC0*NTOK];
__device__ float g_ff1[BB*HID2*NTOK];
__device__ float g_ff3[BB*HID*NTOK];               // gated hidden

#define ACC_N4 ((BB*NHEADS*NTOK*ASTR)/4)           // float4 count = 114688

// ---------------- PDL helpers ----------------------------------------------
#define PDL_SYNC()    cudaGridDependencySynchronize()
#define PDL_TRIGGER() cudaTriggerProgrammaticLaunchCompletion()

// ---------------- small asm helpers ----------------------------------------
__device__ __forceinline__ unsigned smem_u32(const void* p) {
    return (unsigned)__cvta_generic_to_shared(p);
}
__device__ __forceinline__ void ldmx4(unsigned& r0, unsigned& r1, unsigned& r2,
                                      unsigned& r3, unsigned a) {
    asm volatile("ldmatrix.sync.aligned.m8n8.x4.shared.b16 {%0,%1,%2,%3}, [%4];"
                 : "=r"(r0), "=r"(r1), "=r"(r2), "=r"(r3) : "r"(a));
}
__device__ __forceinline__ void ldmx4t(unsigned& r0, unsigned& r1, unsigned& r2,
                                       unsigned& r3, unsigned a) {
    asm volatile("ldmatrix.sync.aligned.m8n8.x4.trans.shared.b16 {%0,%1,%2,%3}, [%4];"
                 : "=r"(r0), "=r"(r1), "=r"(r2), "=r"(r3) : "r"(a));
}
__device__ __forceinline__ void mma16816(float& d0, float& d1, float& d2, float& d3,
                                         unsigned a0, unsigned a1, unsigned a2, unsigned a3,
                                         unsigned b0, unsigned b1) {
    asm volatile("mma.sync.aligned.m16n8k16.row.col.f32.bf16.bf16.f32 "
                 "{%0,%1,%2,%3},{%4,%5,%6,%7},{%8,%9},{%0,%1,%2,%3};"
                 : "+f"(d0), "+f"(d1), "+f"(d2), "+f"(d3)
                 : "r"(a0), "r"(a1), "r"(a2), "r"(a3), "r"(b0), "r"(b1));
}
__device__ __forceinline__ unsigned cvt2(float hi, float lo) {
    unsigned r;
    asm("cvt.rn.bf16x2.f32 %0, %1, %2;" : "=r"(r) : "f"(hi), "f"(lo));
    return r;
}
__device__ __forceinline__ float ex2f(float x) {
    float y; asm("ex2.approx.ftz.f32 %0, %1;" : "=f"(y) : "f"(x)); return y;
}

// ---------------- 1x1 conv (optionally LN in), z-sliced, 128-thread blocks --
template<int CIN, int COUT, int OPT, bool LN>
__global__ void __launch_bounds__(128)
conv1x1_z(const float* __restrict__ in,
          const float* __restrict__ lnw, const float* __restrict__ lnb,
          const float* __restrict__ w,   const float* __restrict__ bias,
          const float* __restrict__ res, float* __restrict__ out,
          float4* zbuf, int zn4)
{
    if (zbuf) {
        int nth  = gridDim.x*gridDim.y*128;
        int ztid = (blockIdx.y*gridDim.x + blockIdx.x)*128 + threadIdx.x;
        float4 z = make_float4(0.f, 0.f, 0.f, 0.f);
        for (int i = ztid; i < zn4; i += nth) zbuf[i] = z;
    }
    __shared__ float ws[CIN*OPT];      // [c][oo]
    const int o0 = blockIdx.y * OPT;
    for (int i = threadIdx.x; i < CIN*OPT; i += 128) {
        int oo = i % OPT, c = i / OPT;
        ws[i] = w[(o0 + oo)*CIN + c];
    }
    __syncthreads();

    PDL_SYNC();

    int pix = blockIdx.x*128 + threadIdx.x;
    int b = pix >> 12, n = pix & (NTOK-1);
    const float* ip = in + (size_t)b*CIN*NTOK + n;

    float acc[OPT];
    #pragma unroll
    for (int oo = 0; oo < OPT; oo++) acc[oo] = bias[o0 + oo];

    if (LN) {
        float v[CIN];
        float s = 0.f, ss = 0.f;
        #pragma unroll
        for (int c = 0; c < CIN; c++) {
            float u = ip[c*NTOK];
            v[c] = u; s += u; ss += u*u;
        }
        float mu  = s * (1.f/CIN);
        float var = ss * (1.f/CIN) - mu*mu;
        float inv = rsqrtf(var + 1e-5f);
        #pragma unroll
        for (int c = 0; c < CIN; c++) {
            float xc = (v[c] - mu)*inv*__ldg(lnw + c) + __ldg(lnb + c);
            #pragma unroll
            for (int oo = 0; oo < OPT; oo++)
                acc[oo] = fmaf(xc, ws[c*OPT + oo], acc[oo]);
        }
    } else {
        #pragma unroll 4
        for (int c = 0; c < CIN; c++) {
            float xc = ip[c*NTOK];
            #pragma unroll
            for (int oo = 0; oo < OPT; oo++)
                acc[oo] = fmaf(xc, ws[c*OPT + oo], acc[oo]);
        }
    }

    PDL_TRIGGER();

    float* op = out + (size_t)(b*COUT + o0)*NTOK + n;
    if (res) {
        const float* rp = res + (size_t)(b*COUT + o0)*NTOK + n;
        #pragma unroll
        for (int oo = 0; oo < OPT; oo++) op[oo*NTOK] = acc[oo] + rp[oo*NTOK];
    } else {
        #pragma unroll
        for (int oo = 0; oo < OPT; oo++) op[oo*NTOK] = acc[oo];
    }
}

// ------- fused: depthwise 3x3 + split/l2norm/temp + bf16 emit --------------
// 2 threads per (bh, token); Q scaled by L2E*t; V col24 = 1.0 (l via mma).
__global__ void __launch_bounds__(128)
dwconv_norm_kernel(const float* __restrict__ in, const float* __restrict__ w,
                   const float* __restrict__ bias, const float* __restrict__ temp,
                   __nv_bfloat16* __restrict__ Q, __nv_bfloat16* __restrict__ K,
                   __nv_bfloat16* __restrict__ V)
{
    int gt   = blockIdx.x*128 + threadIdx.x;         // over BB*NHEADS*NTOK*2
    int half = gt & 1;
    int idx  = gt >> 1;                              // (bh, token)
    int typ  = blockIdx.y;                           // 0=q, 1=k, 2=v
    int n  = idx & (NTOK-1);
    int bh = idx >> 12;
    int b = bh >> 1, hd = bh & 1;
    int x0 = n & 63, y0 = n >> 6;

    int off[9]; bool val[9];
    #pragma unroll
    for (int ky = 0; ky < 3; ky++) {
        int y = y0 + ky - 1;
        #pragma unroll
        for (int kx = 0; kx < 3; kx++) {
            int xx = x0 + kx - 1;
            int t = ky*3 + kx;
            val[t] = ((unsigned)y < 64u) && ((unsigned)xx < 64u);
            off[t] = y*64 + xx;
        }
    }

    PDL_SYNC();

    float buf[12];
    float ss = 0.f;
    int ch0 = typ*CC0 + hd*CHD + half*12;
    #pragma unroll
    for (int c = 0; c < 12; c++) {
        int ch = ch0 + c;
        const float* ip = in + ((size_t)b*C3 + ch)*NTOK;
        const float* wp = w + ch*9;
        float acc = bias[ch];
        #pragma unroll
        for (int tt = 0; tt < 9; tt++) if (val[tt]) acc += wp[tt]*ip[off[tt]];
        buf[c] = acc; ss += acc*acc;
    }
    ss += __shfl_xor_sync(0xffffffffu, ss, 1);       // pair-combine

    const float L2E = 1.4426950408889634f;
    float inv;
    __nv_bfloat16* dst;
    if (typ == 0)      { inv = temp[hd]*L2E / fmaxf(sqrtf(ss), 1e-12f); dst = Q; }
    else if (typ == 1) { inv = 1.f / fmaxf(sqrtf(ss), 1e-12f);          dst = K; }
    else               { inv = 1.f;                                      dst = V; }

    PDL_TRIGGER();

    unsigned tmp[6];
    #pragma unroll
    for (int i = 0; i < 6; i++) tmp[i] = cvt2(buf[2*i+1]*inv, buf[2*i]*inv);
    char* base = (char*)(dst + (size_t)idx*DP) + half*24;
    ((uint2*)base)[0]        = make_uint2(tmp[0], tmp[1]);
    ((uint2*)(base + 8))[0]  = make_uint2(tmp[2], tmp[3]);
    ((uint2*)(base + 16))[0] = make_uint2(tmp[4], tmp[5]);
    if (half) {   // padding cols 24..31 (V gets 1.0 in col 24 -> l via mma)
        unsigned pad0 = (typ == 2) ? cvt2(0.f, 1.f) : 0u;
        *(uint4*)((char*)(dst + (size_t)idx*DP) + 48) = make_uint4(pad0, 0u, 0u, 0u);
    }
}

// ---------------- FFN depthwise 3x3 + gelu gate fused ----------------------
__global__ void dwconv_gate_kernel(const float* __restrict__ in, const float* __restrict__ w,
                                   const float* __restrict__ bias, float* __restrict__ out)
{
    int idx = blockIdx.x*blockDim.x + threadIdx.x;   // over BB*HID*NTOK
    PDL_SYNC();
    if (idx >= BB*HID*NTOK) return;
    int p  = idx & (NTOK-1);
    int bj = idx >> 12;
    int j  = bj % HID;
    int b  = bj / HID;
    int x0 = p & 63, y0 = p >> 6;
    const float* ip1 = in + ((size_t)b*HID2 + j)*NTOK;
    const float* ip2 = in + ((size_t)b*HID2 + HID + j)*NTOK;
    const float* w1 = w + j*9;
    const float* w2 = w + (HID + j)*9;
    float a  = bias[j];
    float g2 = bias[HID + j];
    #pragma unroll
    for (int ky = 0; ky < 3; ky++) {
        int y = y0 + ky - 1;
        if ((unsigned)y < 64u) {
            #pragma unroll
            for (int kx = 0; kx < 3; kx++) {
                int xx = x0 + kx - 1;
                if ((unsigned)xx < 64u) {
                    a  += w1[ky*3 + kx] * ip1[y*64 + xx];
                    g2 += w2[ky*3 + kx] * ip2[y*64 + xx];
                }
            }
        }
    }
    PDL_TRIGGER();
    float g = 0.5f*a*(1.f + erff(a*0.70710678118654752f));
    out[((size_t)b*HID + j)*NTOK + p] = g*g2;
}

// ---------------- bf16 mma.sync flash attention, split-KV, RED epilogue -----
// Q pre-scaled by L2E*t; S accumulators init at -|t|*L2E so p = ex2(c).
// V col 24 = 1 so PV tile 3 computes row-sum l.
#define KVSEG (NTOK/NSPL)   // 512

__global__ void __launch_bounds__(256)
attn_mma_kernel(const __nv_bfloat16* __restrict__ Qb,
                const __nv_bfloat16* __restrict__ Kb,
                const __nv_bfloat16* __restrict__ Vb,
                const float* __restrict__ temp,
                float* __restrict__ acc)
{
    __shared__ __align__(16) unsigned char smem_raw[2*16384];

    int tid  = threadIdx.x;
    int warp = tid >> 5, lane = tid & 31;
    int g    = lane >> 2;
    int t4   = lane & 3;
    int bh   = blockIdx.y;
    int q0   = blockIdx.x * 128;
    int spl  = blockIdx.z;
    int kv0  = spl * KVSEG;

    const float L2E = 1.4426950408889634f;
    float nm = -fabsf(temp[bh & 1]) * L2E;

    PDL_SYNC();    // Q/K/V written by predecessor

    unsigned qf[8];
    {
        const unsigned* q32 = (const unsigned*)(Qb + (size_t)(bh*NTOK + q0 + warp*16)*DP);
        #pragma unroll
        for (int kt = 0; kt < 2; kt++) {
            qf[kt*4+0] = q32[g*16       + kt*8 + t4];
            qf[kt*4+1] = q32[(g+8)*16   + kt*8 + t4];
            qf[kt*4+2] = q32[g*16       + kt*8 + 4 + t4];
            qf[kt*4+3] = q32[(g+8)*16   + kt*8 + 4 + t4];
        }
    }

    float o[16];
    #pragma unroll
    for (int i = 0; i < 16; i++) o[i] = 0.f;

    const uint4* kg = (const uint4*)(Kb + (size_t)bh*NTOK*DP);
    const uint4* vg = (const uint4*)(Vb + (size_t)bh*NTOK*DP);
    int row = tid >> 2, chk = tid & 3;
    unsigned swz = row*128 + ((chk ^ (row & 7))*16);

    uint4 kreg = kg[(kv0 + row)*4 + chk];
    uint4 vreg = vg[(kv0 + row)*4 + chk];
    int it = 0;

    for (int kb = kv0; kb < kv0 + KVSEG; kb += 64) {
        unsigned char* bufK = smem_raw + it*16384;
        unsigned char* bufV = bufK + 8192;
        *(uint4*)(bufK + swz) = kreg;
        *(uint4*)(bufV + swz) = vreg;
        if (kb + 64 < kv0 + KVSEG) {
            kreg = kg[(kb + 64 + row)*4 + chk];
            vreg = vg[(kb + 64 + row)*4 + chk];
        }
        __syncthreads();

        unsigned pb[16];
        #pragma unroll
        for (int j = 0; j < 8; j++) {
            unsigned b0, b1, b2, b3;
            {
                int r = j*8 + (lane & 7);
                int c = lane >> 3;
                unsigned a = smem_u32(bufK + r*128 + ((c ^ (r & 7))*16));
                ldmx4(b0, b1, b2, b3, a);
            }
            float c0 = nm, c1 = nm, c2 = nm, c3 = nm;
            mma16816(c0, c1, c2, c3, qf[0], qf[1], qf[2], qf[3], b0, b1);
            mma16816(c0, c1, c2, c3, qf[4], qf[5], qf[6], qf[7], b2, b3);
            float p0 = ex2f(c0);
            float p1 = ex2f(c1);
            float p2 = ex2f(c2);
            float p3 = ex2f(c3);
            pb[(j>>1)*4 + (j&1)*2 + 0] = cvt2(p1, p0);
            pb[(j>>1)*4 + (j&1)*2 + 1] = cvt2(p3, p2);
        }

        #pragma unroll
        for (int t = 0; t < 4; t++) {
            #pragma unroll
            for (int p = 0; p < 2; p++) {
                unsigned b0, b1, b2, b3;
                {
                    int key = t*16 + ((lane >> 3) & 1)*8 + (lane & 7);
                    int c   = p*2 + (lane >> 4);
                    unsigned a = smem_u32(bufV + key*128 + ((c ^ (key & 7))*16));
                    ldmx4t(b0, b1, b2, b3, a);
                }
                int nn = p*2;
                mma16816(o[nn*4+0], o[nn*4+1], o[nn*4+2], o[nn*4+3],
                         pb[t*4], pb[t*4+1], pb[t*4+2], pb[t*4+3], b0, b1);
                mma16816(o[nn*4+4], o[nn*4+5], o[nn*4+6], o[nn*4+7],
                         pb[t*4], pb[t*4+1], pb[t*4+2], pb[t*4+3], b2, b3);
            }
        }
        it ^= 1;
    }

    PDL_TRIGGER();

    size_t r0 = (size_t)(bh*NTOK + q0 + warp*16 + g);
    float* a0 = acc + r0*ASTR;
    float* a1 = acc + (r0 + 8)*ASTR;
    #pragma unroll
    for (int nn = 0; nn < 3; nn++) {
        int cc = nn*8 + t4*2;
        atomicAdd(a0 + cc,     o[nn*4+0]);
        atomicAdd(a0 + cc + 1, o[nn*4+1]);
        atomicAdd(a1 + cc,     o[nn*4+2]);
        atomicAdd(a1 + cc + 1, o[nn*4+3]);
    }
    if (t4 == 0) { atomicAdd(a0 + 24, o[12]); atomicAdd(a1 + 24, o[14]); }
}

// -------- fused: normalize merged O + proj 1x1 + residual ------------------
// 128-thread blocks, OPT=4, grid (NPIX/128, 48/4) = (64, 12) = 768 CTAs.
__global__ void __launch_bounds__(128)
proj_merge_kernel(const float* __restrict__ acc, const float* __restrict__ x,
                  const float* __restrict__ pw, const float* __restrict__ pb,
                  float* __restrict__ out)
{
    const int OPT = 4;
    __shared__ float ws[CC0*OPT];      // [c][oo]
    const int o0 = blockIdx.y * OPT;
    for (int i = threadIdx.x; i < CC0*OPT; i += 128) {
        int oo = i % OPT, c = i / OPT;
        ws[i] = pw[(o0 + oo)*CC0 + c];
    }
    __syncthreads();

    PDL_SYNC();    // attn atomics must be complete

    int pix = blockIdx.x*128 + threadIdx.x;
    int b = pix >> 12, n = pix & (NTOK-1);

    float accv[OPT];
    #pragma unroll
    for (int oo = 0; oo < OPT; oo++) accv[oo] = pb[o0 + oo];

    #pragma unroll
    for (int hd = 0; hd < NHEADS; hd++) {
        float h[25];
        const float4* r = (const float4*)(acc + ((size_t)(b*NHEADS + hd)*NTOK + n)*ASTR);
        #pragma unroll
        for (int i = 0; i < 6; i++) {
            float4 q = r[i];
            h[i*4+0]=q.x; h[i*4+1]=q.y; h[i*4+2]=q.z; h[i*4+3]=q.w;
        }
        h[24] = r[6].x;
        float inv = 1.f / h[24];
        #pragma unroll
        for (int c = 0; c < CHD; c++) {
            float xc = h[c]*inv;
            #pragma unroll
            for (int oo = 0; oo < OPT; oo++)
                accv[oo] = fmaf(xc, ws[(hd*CHD + c)*OPT + oo], accv[oo]);
        }
    }

    PDL_TRIGGER();

    float* op = out + (size_t)(b*CC0 + o0)*NTOK + n;
    const float* rp = x + (size_t)(b*CC0 + o0)*NTOK + n;
    #pragma unroll
    for (int oo = 0; oo < OPT; oo++) op[oo*NTOK] = accv[oo] + rp[oo*NTOK];
}

// ---------------- launch ----------------------------------------------------
extern "C" void kernel_launch(void* const* d_in, const int* in_sizes, int n_in,
                              void* d_out, int out_size)
{
    const float* x    = (const float*)d_in[0];
    const float* n1w  = (const float*)d_in[1];
    const float* n1b  = (const float*)d_in[2];
    const float* qkvw = (const float*)d_in[3];
    const float* qkvb = (const float*)d_in[4];
    const float* qdww = (const float*)d_in[5];
    const float* qdwb = (const float*)d_in[6];
    const float* temp = (const float*)d_in[7];
    const float* pw   = (const float*)d_in[8];
    const float* pb   = (const float*)d_in[9];
    const float* n2w  = (const float*)d_in[10];
    const float* n2b  = (const float*)d_in[11];
    const float* fiw  = (const float*)d_in[12];
    const float* fib  = (const float*)d_in[13];
    const float* fdww = (const float*)d_in[14];
    const float* fdwb = (const float*)d_in[15];
    const float* fow  = (const float*)d_in[16];
    const float* fob  = (const float*)d_in[17];
    float* out = (float*)d_out;

    float *qkv1, *accp, *x1, *ff1, *ff3;
    __nv_bfloat16 *Qp, *Kp, *Vp;
    cudaGetSymbolAddress((void**)&qkv1, g_qkv1);
    cudaGetSymbolAddress((void**)&Qp,   g_qb);
    cudaGetSymbolAddress((void**)&Kp,   g_kb);
    cudaGetSymbolAddress((void**)&Vp,   g_vb);
    cudaGetSymbolAddress((void**)&accp, g_acc);
    cudaGetSymbolAddress((void**)&x1,   g_x1);
    cudaGetSymbolAddress((void**)&ff1,  g_ff1);
    cudaGetSymbolAddress((void**)&ff3,  g_ff3);

    cudaLaunchAttribute pss[1];
    pss[0].id = cudaLaunchAttributeProgrammaticStreamSerialization;
    pss[0].val.programmaticStreamSerializationAllowed = 1;

    auto cfg = [&](unsigned gx, unsigned gy, unsigned bd) {
        cudaLaunchConfig_t c = {};
        c.gridDim  = dim3(gx, gy, 1);
        c.blockDim = dim3(bd, 1, 1);
        c.dynamicSmemBytes = 0;
        c.stream = 0;
        c.attrs = pss;
        c.numAttrs = 1;
        return c;
    };

    // 1. LN1 + qkv 1x1 (also zeroes attn accumulator) — now PSS too: the PDL
    //    chain guarantees prev replay's g_acc/qkv1 readers finished before
    //    prev kernel 7 triggers; prologue (zero + weights) touches only
    //    scratch/host inputs, data reads follow PDL_SYNC.
    {
        cudaLaunchConfig_t c = cfg(NPIX/128, C3/8, 128);
        cudaLaunchKernelEx(&c, conv1x1_z<CC0, C3, 8, true>,
            x, n1w, n1b, qkvw, qkvb, (const float*)nullptr, qkv1,
            (float4*)accp, (int)ACC_N4);
    }
    // 2. fused depthwise 3x3 + split/l2norm/bf16
    {
        cudaLaunchConfig_t c = cfg((BB*NHEADS*NTOK*2)/128, 3, 128);
        cudaLaunchKernelEx(&c, dwconv_norm_kernel,
            (const float*)qkv1, qdww, qdwb, temp, Qp, Kp, Vp);
    }
    // 3. flash attention, split-KV, RED merge into g_acc
    {
        cudaLaunchConfig_t c = cfg(NTOK/128, BB*NHEADS, 256);
        c.gridDim.z = NSPL;
        cudaLaunchKernelEx(&c, attn_mma_kernel,
            (const __nv_bfloat16*)Qp, (const __nv_bfloat16*)Kp,
            (const __nv_bfloat16*)Vp, temp, accp);
    }
    // 4. normalize + proj 1x1 + residual -> g_x1
    {
        cudaLaunchConfig_t c = cfg(NPIX/128, CC0/4, 128);
        cudaLaunchKernelEx(&c, proj_merge_kernel,
            (const float*)accp, x, pw, pb, x1);
    }
    // 5. LN2 + fi 1x1 -> g_ff1
    {
        cudaLaunchConfig_t c = cfg(NPIX/128, HID2/12, 128);
        cudaLaunchKernelEx(&c, conv1x1_z<CC0, HID2, 12, true>,
            (const float*)x1, n2w, n2b, fiw, fib, (const float*)nullptr, ff1,
            (float4*)nullptr, 0);
    }
    // 6. FFN depthwise + gelu gate -> g_ff3
    {
        cudaLaunchConfig_t c = cfg((BB*HID*NTOK + 255)/256, 1, 256);
        cudaLaunchKernelEx(&c, dwconv_gate_kernel,
            (const float*)ff1, fdww, fdwb, ff3);
    }
    // 7. fo 1x1 + residual -> out
    {
        cudaLaunchConfig_t c = cfg(NPIX/128, CC0/6, 128);
        cudaLaunchKernelEx(&c, conv1x1_z<HID, CC0, 6, false>,
            (const float*)ff3, (const float*)nullptr, (const float*)nullptr,
            fow, fob, (const float*)x1, out, (float4*)nullptr, 0);
    }
}

// round 17
// speedup vs baseline: 1.0188x; 1.0188x over previous
#include <cuda_runtime.h>
#include <cuda_bf16.h>
#include <math.h>

// ---------------- problem constants ----------------
#define BB      2
#define CC0     48          // dim
#define NHEADS  2
#define CHD     24          // channels per head
#define DP      32          // padded head dim (bf16 tensors)
#define NTOK    4096        // 64*64
#define NPIX    (BB*NTOK)   // 8192
#define C3      144         // dim*3
#define HID     96
#define HID2    192
#define NSPL    8           // attention KV splits
#define ASTR    28          // accumulator record (floats, 16B aligned): 24 O + l

// ---------------- scratch (device globals; no allocation allowed) ----------
__device__ float g_qkv1[BB*C3*NTOK];
__device__ __nv_bfloat16 g_qb[BB*NHEADS*NTOK*DP];
__device__ __nv_bfloat16 g_kb[BB*NHEADS*NTOK*DP];
__device__ __nv_bfloat16 g_vb[BB*NHEADS*NTOK*DP];
__device__ float g_acc[BB*NHEADS*NTOK*ASTR];       // atomic O/l accumulator
__device__ float g_x1[BB*CC0*NTOK];
__device__ float g_ff1[BB*HID2*NTOK];
__device__ float g_ff3[BB*HID*NTOK];               // gated hidden

#define ACC_N4 ((BB*NHEADS*NTOK*ASTR)/4)           // float4 count = 114688

// ---------------- PDL helpers ----------------------------------------------
#define PDL_SYNC()    cudaGridDependencySynchronize()
#define PDL_TRIGGER() cudaTriggerProgrammaticLaunchCompletion()

// ---------------- small asm helpers ----------------------------------------
__device__ __forceinline__ unsigned smem_u32(const void* p) {
    return (unsigned)__cvta_generic_to_shared(p);
}
__device__ __forceinline__ void ldmx4(unsigned& r0, unsigned& r1, unsigned& r2,
                                      unsigned& r3, unsigned a) {
    asm volatile("ldmatrix.sync.aligned.m8n8.x4.shared.b16 {%0,%1,%2,%3}, [%4];"
                 : "=r"(r0), "=r"(r1), "=r"(r2), "=r"(r3) : "r"(a));
}
__device__ __forceinline__ void ldmx4t(unsigned& r0, unsigned& r1, unsigned& r2,
                                       unsigned& r3, unsigned a) {
    asm volatile("ldmatrix.sync.aligned.m8n8.x4.trans.shared.b16 {%0,%1,%2,%3}, [%4];"
                 : "=r"(r0), "=r"(r1), "=r"(r2), "=r"(r3) : "r"(a));
}
__device__ __forceinline__ void mma16816(float& d0, float& d1, float& d2, float& d3,
                                         unsigned a0, unsigned a1, unsigned a2, unsigned a3,
                                         unsigned b0, unsigned b1) {
    asm volatile("mma.sync.aligned.m16n8k16.row.col.f32.bf16.bf16.f32 "
                 "{%0,%1,%2,%3},{%4,%5,%6,%7},{%8,%9},{%0,%1,%2,%3};"
                 : "+f"(d0), "+f"(d1), "+f"(d2), "+f"(d3)
                 : "r"(a0), "r"(a1), "r"(a2), "r"(a3), "r"(b0), "r"(b1));
}
__device__ __forceinline__ unsigned cvt2(float hi, float lo) {
    unsigned r;
    asm("cvt.rn.bf16x2.f32 %0, %1, %2;" : "=r"(r) : "f"(hi), "f"(lo));
    return r;
}
__device__ __forceinline__ float ex2f(float x) {
    float y; asm("ex2.approx.ftz.f32 %0, %1;" : "=f"(y) : "f"(x)); return y;
}

// ---------------- 1x1 conv (optionally LN in), z-sliced, 128-thread blocks --
template<int CIN, int COUT, int OPT, bool LN>
__global__ void __launch_bounds__(128)
conv1x1_z(const float* __restrict__ in,
          const float* __restrict__ lnw, const float* __restrict__ lnb,
          const float* __restrict__ w,   const float* __restrict__ bias,
          const float* __restrict__ res, float* __restrict__ out,
          float4* zbuf, int zn4)
{
    if (zbuf) {
        int nth  = gridDim.x*gridDim.y*128;
        int ztid = (blockIdx.y*gridDim.x + blockIdx.x)*128 + threadIdx.x;
        float4 z = make_float4(0.f, 0.f, 0.f, 0.f);
        for (int i = ztid; i < zn4; i += nth) zbuf[i] = z;
    }
    __shared__ float ws[CIN*OPT];      // [c][oo]
    const int o0 = blockIdx.y * OPT;
    for (int i = threadIdx.x; i < CIN*OPT; i += 128) {
        int oo = i % OPT, c = i / OPT;
        ws[i] = w[(o0 + oo)*CIN + c];
    }
    __syncthreads();

    PDL_SYNC();

    int pix = blockIdx.x*128 + threadIdx.x;
    int b = pix >> 12, n = pix & (NTOK-1);
    const float* ip = in + (size_t)b*CIN*NTOK + n;

    float acc[OPT];
    #pragma unroll
    for (int oo = 0; oo < OPT; oo++) acc[oo] = bias[o0 + oo];

    if (LN) {
        float v[CIN];
        float s = 0.f, ss = 0.f;
        #pragma unroll
        for (int c = 0; c < CIN; c++) {
            float u = ip[c*NTOK];
            v[c] = u; s += u; ss += u*u;
        }
        float mu  = s * (1.f/CIN);
        float var = ss * (1.f/CIN) - mu*mu;
        float inv = rsqrtf(var + 1e-5f);
        #pragma unroll
        for (int c = 0; c < CIN; c++) {
            float xc = (v[c] - mu)*inv*__ldg(lnw + c) + __ldg(lnb + c);
            #pragma unroll
            for (int oo = 0; oo < OPT; oo++)
                acc[oo] = fmaf(xc, ws[c*OPT + oo], acc[oo]);
        }
    } else {
        #pragma unroll 4
        for (int c = 0; c < CIN; c++) {
            float xc = ip[c*NTOK];
            #pragma unroll
            for (int oo = 0; oo < OPT; oo++)
                acc[oo] = fmaf(xc, ws[c*OPT + oo], acc[oo]);
        }
    }

    PDL_TRIGGER();

    float* op = out + (size_t)(b*COUT + o0)*NTOK + n;
    if (res) {
        const float* rp = res + (size_t)(b*COUT + o0)*NTOK + n;
        #pragma unroll
        for (int oo = 0; oo < OPT; oo++) op[oo*NTOK] = acc[oo] + rp[oo*NTOK];
    } else {
        #pragma unroll
        for (int oo = 0; oo < OPT; oo++) op[oo*NTOK] = acc[oo];
    }
}

// ------- fused: depthwise 3x3 + split/l2norm/temp + bf16 emit --------------
// 2 threads per (bh, token); Q scaled by L2E*t; V col24 = 1.0 (l via mma).
__global__ void __launch_bounds__(128)
dwconv_norm_kernel(const float* __restrict__ in, const float* __restrict__ w,
                   const float* __restrict__ bias, const float* __restrict__ temp,
                   __nv_bfloat16* __restrict__ Q, __nv_bfloat16* __restrict__ K,
                   __nv_bfloat16* __restrict__ V)
{
    int gt   = blockIdx.x*128 + threadIdx.x;         // over BB*NHEADS*NTOK*2
    int half = gt & 1;
    int idx  = gt >> 1;                              // (bh, token)
    int typ  = blockIdx.y;                           // 0=q, 1=k, 2=v
    int n  = idx & (NTOK-1);
    int bh = idx >> 12;
    int b = bh >> 1, hd = bh & 1;
    int x0 = n & 63, y0 = n >> 6;

    int off[9]; bool val[9];
    #pragma unroll
    for (int ky = 0; ky < 3; ky++) {
        int y = y0 + ky - 1;
        #pragma unroll
        for (int kx = 0; kx < 3; kx++) {
            int xx = x0 + kx - 1;
            int t = ky*3 + kx;
            val[t] = ((unsigned)y < 64u) && ((unsigned)xx < 64u);
            off[t] = y*64 + xx;
        }
    }

    PDL_SYNC();

    float buf[12];
    float ss = 0.f;
    int ch0 = typ*CC0 + hd*CHD + half*12;
    #pragma unroll
    for (int c = 0; c < 12; c++) {
        int ch = ch0 + c;
        const float* ip = in + ((size_t)b*C3 + ch)*NTOK;
        const float* wp = w + ch*9;
        float acc = bias[ch];
        #pragma unroll
        for (int tt = 0; tt < 9; tt++) if (val[tt]) acc += wp[tt]*ip[off[tt]];
        buf[c] = acc; ss += acc*acc;
    }
    ss += __shfl_xor_sync(0xffffffffu, ss, 1);       // pair-combine

    const float L2E = 1.4426950408889634f;
    float inv;
    __nv_bfloat16* dst;
    if (typ == 0)      { inv = temp[hd]*L2E / fmaxf(sqrtf(ss), 1e-12f); dst = Q; }
    else if (typ == 1) { inv = 1.f / fmaxf(sqrtf(ss), 1e-12f);          dst = K; }
    else               { inv = 1.f;                                      dst = V; }

    PDL_TRIGGER();

    unsigned tmp[6];
    #pragma unroll
    for (int i = 0; i < 6; i++) tmp[i] = cvt2(buf[2*i+1]*inv, buf[2*i]*inv);
    char* base = (char*)(dst + (size_t)idx*DP) + half*24;
    ((uint2*)base)[0]        = make_uint2(tmp[0], tmp[1]);
    ((uint2*)(base + 8))[0]  = make_uint2(tmp[2], tmp[3]);
    ((uint2*)(base + 16))[0] = make_uint2(tmp[4], tmp[5]);
    if (half) {   // padding cols 24..31 (V gets 1.0 in col 24 -> l via mma)
        unsigned pad0 = (typ == 2) ? cvt2(0.f, 1.f) : 0u;
        *(uint4*)((char*)(dst + (size_t)idx*DP) + 48) = make_uint4(pad0, 0u, 0u, 0u);
    }
}

// ---------------- FFN depthwise 3x3 + gelu gate fused ----------------------
__global__ void dwconv_gate_kernel(const float* __restrict__ in, const float* __restrict__ w,
                                   const float* __restrict__ bias, float* __restrict__ out)
{
    int idx = blockIdx.x*blockDim.x + threadIdx.x;   // over BB*HID*NTOK
    PDL_SYNC();
    if (idx >= BB*HID*NTOK) return;
    int p  = idx & (NTOK-1);
    int bj = idx >> 12;
    int j  = bj % HID;
    int b  = bj / HID;
    int x0 = p & 63, y0 = p >> 6;
    const float* ip1 = in + ((size_t)b*HID2 + j)*NTOK;
    const float* ip2 = in + ((size_t)b*HID2 + HID + j)*NTOK;
    const float* w1 = w + j*9;
    const float* w2 = w + (HID + j)*9;
    float a  = bias[j];
    float g2 = bias[HID + j];
    #pragma unroll
    for (int ky = 0; ky < 3; ky++) {
        int y = y0 + ky - 1;
        if ((unsigned)y < 64u) {
            #pragma unroll
            for (int kx = 0; kx < 3; kx++) {
                int xx = x0 + kx - 1;
                if ((unsigned)xx < 64u) {
                    a  += w1[ky*3 + kx] * ip1[y*64 + xx];
                    g2 += w2[ky*3 + kx] * ip2[y*64 + xx];
                }
            }
        }
    }
    PDL_TRIGGER();
    float g = 0.5f*a*(1.f + erff(a*0.70710678118654752f));
    out[((size_t)b*HID + j)*NTOK + p] = g*g2;
}

// ---------------- bf16 mma.sync flash attention, split-KV, RED epilogue -----
// Q pre-scaled by L2E*t; S accumulators init at -|t|*L2E so p = ex2(c).
// V col 24 = 1 so PV tile 3 computes row-sum l.
#define KVSEG (NTOK/NSPL)   // 512

__global__ void __launch_bounds__(256)
attn_mma_kernel(const __nv_bfloat16* __restrict__ Qb,
                const __nv_bfloat16* __restrict__ Kb,
                const __nv_bfloat16* __restrict__ Vb,
                const float* __restrict__ temp,
                float* __restrict__ acc)
{
    __shared__ __align__(16) unsigned char smem_raw[2*16384];

    int tid  = threadIdx.x;
    int warp = tid >> 5, lane = tid & 31;
    int g    = lane >> 2;
    int t4   = lane & 3;
    int bh   = blockIdx.y;
    int q0   = blockIdx.x * 128;
    int spl  = blockIdx.z;
    int kv0  = spl * KVSEG;

    const float L2E = 1.4426950408889634f;
    float nm = -fabsf(temp[bh & 1]) * L2E;

    PDL_SYNC();    // Q/K/V written by predecessor

    unsigned qf[8];
    {
        const unsigned* q32 = (const unsigned*)(Qb + (size_t)(bh*NTOK + q0 + warp*16)*DP);
        #pragma unroll
        for (int kt = 0; kt < 2; kt++) {
            qf[kt*4+0] = q32[g*16       + kt*8 + t4];
            qf[kt*4+1] = q32[(g+8)*16   + kt*8 + t4];
            qf[kt*4+2] = q32[g*16       + kt*8 + 4 + t4];
            qf[kt*4+3] = q32[(g+8)*16   + kt*8 + 4 + t4];
        }
    }

    float o[16];
    #pragma unroll
    for (int i = 0; i < 16; i++) o[i] = 0.f;

    const uint4* kg = (const uint4*)(Kb + (size_t)bh*NTOK*DP);
    const uint4* vg = (const uint4*)(Vb + (size_t)bh*NTOK*DP);
    int row = tid >> 2, chk = tid & 3;
    unsigned swz = row*128 + ((chk ^ (row & 7))*16);

    uint4 kreg = kg[(kv0 + row)*4 + chk];
    uint4 vreg = vg[(kv0 + row)*4 + chk];
    int it = 0;

    for (int kb = kv0; kb < kv0 + KVSEG; kb += 64) {
        unsigned char* bufK = smem_raw + it*16384;
        unsigned char* bufV = bufK + 8192;
        *(uint4*)(bufK + swz) = kreg;
        *(uint4*)(bufV + swz) = vreg;
        if (kb + 64 < kv0 + KVSEG) {
            kreg = kg[(kb + 64 + row)*4 + chk];
            vreg = vg[(kb + 64 + row)*4 + chk];
        }
        __syncthreads();

        unsigned pb[16];
        #pragma unroll
        for (int j = 0; j < 8; j++) {
            unsigned b0, b1, b2, b3;
            {
                int r = j*8 + (lane & 7);
                int c = lane >> 3;
                unsigned a = smem_u32(bufK + r*128 + ((c ^ (r & 7))*16));
                ldmx4(b0, b1, b2, b3, a);
            }
            float c0 = nm, c1 = nm, c2 = nm, c3 = nm;
            mma16816(c0, c1, c2, c3, qf[0], qf[1], qf[2], qf[3], b0, b1);
            mma16816(c0, c1, c2, c3, qf[4], qf[5], qf[6], qf[7], b2, b3);
            float p0 = ex2f(c0);
            float p1 = ex2f(c1);
            float p2 = ex2f(c2);
            float p3 = ex2f(c3);
            pb[(j>>1)*4 + (j&1)*2 + 0] = cvt2(p1, p0);
            pb[(j>>1)*4 + (j&1)*2 + 1] = cvt2(p3, p2);
        }

        #pragma unroll
        for (int t = 0; t < 4; t++) {
            #pragma unroll
            for (int p = 0; p < 2; p++) {
                unsigned b0, b1, b2, b3;
                {
                    int key = t*16 + ((lane >> 3) & 1)*8 + (lane & 7);
                    int c   = p*2 + (lane >> 4);
                    unsigned a = smem_u32(bufV + key*128 + ((c ^ (key & 7))*16));
                    ldmx4t(b0, b1, b2, b3, a);
                }
                int nn = p*2;
                mma16816(o[nn*4+0], o[nn*4+1], o[nn*4+2], o[nn*4+3],
                         pb[t*4], pb[t*4+1], pb[t*4+2], pb[t*4+3], b0, b1);
                mma16816(o[nn*4+4], o[nn*4+5], o[nn*4+6], o[nn*4+7],
                         pb[t*4], pb[t*4+1], pb[t*4+2], pb[t*4+3], b2, b3);
            }
        }
        it ^= 1;
    }

    PDL_TRIGGER();

    size_t r0 = (size_t)(bh*NTOK + q0 + warp*16 + g);
    float* a0 = acc + r0*ASTR;
    float* a1 = acc + (r0 + 8)*ASTR;
    #pragma unroll
    for (int nn = 0; nn < 3; nn++) {
        int cc = nn*8 + t4*2;
        atomicAdd(a0 + cc,     o[nn*4+0]);
        atomicAdd(a0 + cc + 1, o[nn*4+1]);
        atomicAdd(a1 + cc,     o[nn*4+2]);
        atomicAdd(a1 + cc + 1, o[nn*4+3]);
    }
    if (t4 == 0) { atomicAdd(a0 + 24, o[12]); atomicAdd(a1 + 24, o[14]); }
}

// -------- fused: normalize merged O + proj 1x1 + residual ------------------
// 128-thread blocks, OPT=4, grid (NPIX/128, 48/4) = (64, 12) = 768 CTAs.
__global__ void __launch_bounds__(128)
proj_merge_kernel(const float* __restrict__ acc, const float* __restrict__ x,
                  const float* __restrict__ pw, const float* __restrict__ pb,
                  float* __restrict__ out)
{
    const int OPT = 4;
    __shared__ float ws[CC0*OPT];      // [c][oo]
    const int o0 = blockIdx.y * OPT;
    for (int i = threadIdx.x; i < CC0*OPT; i += 128) {
        int oo = i % OPT, c = i / OPT;
        ws[i] = pw[(o0 + oo)*CC0 + c];
    }
    __syncthreads();

    PDL_SYNC();    // attn atomics must be complete

    int pix = blockIdx.x*128 + threadIdx.x;
    int b = pix >> 12, n = pix & (NTOK-1);

    float accv[OPT];
    #pragma unroll
    for (int oo = 0; oo < OPT; oo++) accv[oo] = pb[o0 + oo];

    #pragma unroll
    for (int hd = 0; hd < NHEADS; hd++) {
        float h[25];
        const float4* r = (const float4*)(acc + ((size_t)(b*NHEADS + hd)*NTOK + n)*ASTR);
        #pragma unroll
        for (int i = 0; i < 6; i++) {
            float4 q = r[i];
            h[i*4+0]=q.x; h[i*4+1]=q.y; h[i*4+2]=q.z; h[i*4+3]=q.w;
        }
        h[24] = r[6].x;
        float inv = 1.f / h[24];
        #pragma unroll
        for (int c = 0; c < CHD; c++) {
            float xc = h[c]*inv;
            #pragma unroll
            for (int oo = 0; oo < OPT; oo++)
                accv[oo] = fmaf(xc, ws[(hd*CHD + c)*OPT + oo], accv[oo]);
        }
    }

    PDL_TRIGGER();

    float* op = out + (size_t)(b*CC0 + o0)*NTOK + n;
    const float* rp = x + (size_t)(b*CC0 + o0)*NTOK + n;
    #pragma unroll
    for (int oo = 0; oo < OPT; oo++) op[oo*NTOK] = accv[oo] + rp[oo*NTOK];
}

// ---------------- launch ----------------------------------------------------
extern "C" void kernel_launch(void* const* d_in, const int* in_sizes, int n_in,
                              void* d_out, int out_size)
{
    const float* x    = (const float*)d_in[0];
    const float* n1w  = (const float*)d_in[1];
    const float* n1b  = (const float*)d_in[2];
    const float* qkvw = (const float*)d_in[3];
    const float* qkvb = (const float*)d_in[4];
    const float* qdww = (const float*)d_in[5];
    const float* qdwb = (const float*)d_in[6];
    const float* temp = (const float*)d_in[7];
    const float* pw   = (const float*)d_in[8];
    const float* pb   = (const float*)d_in[9];
    const float* n2w  = (const float*)d_in[10];
    const float* n2b  = (const float*)d_in[11];
    const float* fiw  = (const float*)d_in[12];
    const float* fib  = (const float*)d_in[13];
    const float* fdww = (const float*)d_in[14];
    const float* fdwb = (const float*)d_in[15];
    const float* fow  = (const float*)d_in[16];
    const float* fob  = (const float*)d_in[17];
    float* out = (float*)d_out;

    float *qkv1, *accp, *x1, *ff1, *ff3;
    __nv_bfloat16 *Qp, *Kp, *Vp;
    cudaGetSymbolAddress((void**)&qkv1, g_qkv1);
    cudaGetSymbolAddress((void**)&Qp,   g_qb);
    cudaGetSymbolAddress((void**)&Kp,   g_kb);
    cudaGetSymbolAddress((void**)&Vp,   g_vb);
    cudaGetSymbolAddress((void**)&accp, g_acc);
    cudaGetSymbolAddress((void**)&x1,   g_x1);
    cudaGetSymbolAddress((void**)&ff1,  g_ff1);
    cudaGetSymbolAddress((void**)&ff3,  g_ff3);

    cudaLaunchAttribute pss[1];
    pss[0].id = cudaLaunchAttributeProgrammaticStreamSerialization;
    pss[0].val.programmaticStreamSerializationAllowed = 1;

    auto cfg = [&](unsigned gx, unsigned gy, unsigned bd, bool pdl) {
        cudaLaunchConfig_t c = {};
        c.gridDim  = dim3(gx, gy, 1);
        c.blockDim = dim3(bd, 1, 1);
        c.dynamicSmemBytes = 0;
        c.stream = 0;
        c.attrs = pdl ? pss : nullptr;
        c.numAttrs = pdl ? 1 : 0;
        return c;
    };

    // 1. LN1 + qkv 1x1 (also zeroes attn accumulator) — NO PSS
    {
        cudaLaunchConfig_t c = cfg(NPIX/128, C3/8, 128, false);
        cudaLaunchKernelEx(&c, conv1x1_z<CC0, C3, 8, true>,
            x, n1w, n1b, qkvw, qkvb, (const float*)nullptr, qkv1,
            (float4*)accp, (int)ACC_N4);
    }
    // 2. fused depthwise 3x3 + split/l2norm/bf16
    {
        cudaLaunchConfig_t c = cfg((BB*NHEADS*NTOK*2)/128, 3, 128, true);
        cudaLaunchKernelEx(&c, dwconv_norm_kernel,
            (const float*)qkv1, qdww, qdwb, temp, Qp, Kp, Vp);
    }
    // 3. flash attention, split-KV, RED merge into g_acc
    {
        cudaLaunchConfig_t c = cfg(NTOK/128, BB*NHEADS, 256, true);
        c.gridDim.z = NSPL;
        cudaLaunchKernelEx(&c, attn_mma_kernel,
            (const __nv_bfloat16*)Qp, (const __nv_bfloat16*)Kp,
            (const __nv_bfloat16*)Vp, temp, accp);
    }
    // 4. normalize + proj 1x1 + residual -> g_x1
    {
        cudaLaunchConfig_t c = cfg(NPIX/128, CC0/4, 128, true);
        cudaLaunchKernelEx(&c, proj_merge_kernel,
            (const float*)accp, x, pw, pb, x1);
    }
    // 5. LN2 + fi 1x1 -> g_ff1
    {
        cudaLaunchConfig_t c = cfg(NPIX/128, HID2/12, 128, true);
        cudaLaunchKernelEx(&c, conv1x1_z<CC0, HID2, 12, true>,
            (const float*)x1, n2w, n2b, fiw, fib, (const float*)nullptr, ff1,
            (float4*)nullptr, 0);
    }
    // 6. FFN depthwise + gelu gate -> g_ff3
    {
        cudaLaunchConfig_t c = cfg((BB*HID*NTOK + 255)/256, 1, 256, true);
        cudaLaunchKernelEx(&c, dwconv_gate_kernel,
            (const float*)ff1, fdww, fdwb, ff3);
    }
    // 7. fo 1x1 + residual -> out
    {
        cudaLaunchConfig_t c = cfg(NPIX/128, CC0/6, 128, true);
        cudaLaunchKernelEx(&c, conv1x1_z<HID, CC0, 6, false>,
            (const float*)ff3, (const float*)nullptr, (const float*)nullptr,
            fow, fob, (const float*)x1, out, (float4*)nullptr, 0);
    }
}